// round 15
// baseline (speedup 1.0000x reference)
#include <cuda_runtime.h>
#include <cuda_fp16.h>
#include <math.h>

#define BATCH 4
#define SEQ   2048
#define NH    16
#define HD    128
#define DM    2048
#define MROWS (BATCH*SEQ)
#define KDIM  2048
#define NCHUNK (KDIM/64)
#define ATT_SCALE 0.08838834764831845f
#define QSCALE (ATT_SCALE * 1.4426950408889634f)   // fold log2(e) for ex2 softmax
#define NEG_L2_ROPE (-0.103810253123f)   // -log2(10000)/128

// ---------------------------------------------------------------------------
// scratch (device globals; no cudaMalloc anywhere)
// ---------------------------------------------------------------------------
__device__ __half g_a16[(size_t)MROWS*DM];   // activations fp16 (x, then attn out)
__device__ __half g_wqT[(size_t)DM*DM];      // weights, transposed, single fp16
__device__ __half g_woT[(size_t)DM*DM];
__device__ __half g_wkT[(size_t)HD*DM];
__device__ __half g_wvT[(size_t)HD*DM];
// attention operands (single fp16); q pre-scaled by QSCALE
__device__ __half g_qh[(size_t)MROWS*DM];    // [B,S,NH,HD]
__device__ __half g_kh16[(size_t)MROWS*HD];  // [B,S,HD]
__device__ __half g_vt16[(size_t)MROWS*HD];  // [B,HD,S]

// ---------------------------------------------------------------------------
// helpers
// ---------------------------------------------------------------------------
__device__ __forceinline__ unsigned s2u(const void* p) {
    unsigned a;
    asm("{ .reg .u64 t; cvta.to.shared.u64 t, %1; cvt.u32.u64 %0, t; }"
        : "=r"(a) : "l"(p));
    return a;
}
__device__ __forceinline__ void ldmx4(unsigned r[4], unsigned addr) {
    asm volatile("ldmatrix.sync.aligned.m8n8.x4.shared.b16 {%0,%1,%2,%3}, [%4];"
                 : "=r"(r[0]), "=r"(r[1]), "=r"(r[2]), "=r"(r[3]) : "r"(addr));
}
__device__ __forceinline__ void mma_f16(float c[4], const unsigned a[4],
                                        const unsigned b[2]) {
    asm volatile(
        "mma.sync.aligned.m16n8k16.row.col.f32.f16.f16.f32 "
        "{%0,%1,%2,%3}, {%4,%5,%6,%7}, {%8,%9}, {%0,%1,%2,%3};"
        : "+f"(c[0]), "+f"(c[1]), "+f"(c[2]), "+f"(c[3])
        : "r"(a[0]), "r"(a[1]), "r"(a[2]), "r"(a[3]), "r"(b[0]), "r"(b[1]));
}
__device__ __forceinline__ unsigned pack_h2(float a, float b) {
    __half2 t = __floats2half2_rn(a, b);
    return *(unsigned*)&t;
}
__device__ __forceinline__ float ex2f(float x) {
    float r;
    asm("ex2.approx.f32 %0, %1;" : "=f"(r) : "f"(x));
    return r;
}
__device__ __forceinline__ void cpa16(unsigned dst, const void* src) {
    asm volatile("cp.async.cg.shared.global [%0], [%1], 16;"
                 :: "r"(dst), "l"(src) : "memory");
}
__device__ __forceinline__ void cp_commit() {
    asm volatile("cp.async.commit_group;" ::: "memory");
}
template<int N> __device__ __forceinline__ void cp_wait() {
    asm volatile("cp.async.wait_group %0;" :: "n"(N) : "memory");
}

// ---------------------------------------------------------------------------
// pure fp16 GEMM mainloop, 256(M) x 128(N) tile: acc = A[256,K] @ B[128,K]^T.
// 256 threads; warp tile 64(M) x 64(N). 3-stage cp.async ring (48 KB/stage).
// ---------------------------------------------------------------------------
#define GSTG 49152u   // stage bytes: A 32K | B 16K

__device__ __forceinline__ void gemm_mainloop(
    const __half* __restrict__ A, const __half* __restrict__ B,
    int m0, int n0, char* smem, float acc[4][8][4])
{
    const unsigned sb = s2u(smem);
    const int tid = threadIdx.x;
    const int lane = tid & 31, w = tid >> 5;
    const int wm = w & 3, wn = w >> 2;

    #pragma unroll
    for (int mt = 0; mt < 4; mt++)
        #pragma unroll
        for (int j = 0; j < 8; j++)
            #pragma unroll
            for (int e = 0; e < 4; e++) acc[mt][j][e] = 0.f;

    int arow[4];
    #pragma unroll
    for (int mt = 0; mt < 4; mt++)
        arow[mt] = wm*64 + mt*16 + (lane & 7) + ((lane >> 3) & 1) * 8;
    const int acolh = (lane >> 4) * 16;
    const int brow4 = wn*64 + (lane & 7) + ((lane >> 4) & 1) * 8;
    const int bcol8 = ((lane >> 3) & 1) * 16;

    auto load_chunk = [&](int c, int st) {
        const int k0 = c * 64;
        const unsigned base = sb + (unsigned)st * GSTG;
        #pragma unroll
        for (int t = 0; t < 8; t++) {          // A: 256 rows x 128B
            int i = tid + t * 256;
            int rr = i >> 3, q = i & 7;
            size_t ga = (size_t)(m0 + rr) * KDIM + k0 + q * 8;
            int so = rr * 128 + q * 16;
            int sw = so ^ ((so >> 3) & 0x70);
            cpa16(base + sw, A + ga);
        }
        #pragma unroll
        for (int t = 0; t < 4; t++) {          // B: 128 rows x 128B
            int i = tid + t * 256;
            int rr = i >> 3, q = i & 7;
            size_t gb = (size_t)(n0 + rr) * KDIM + k0 + q * 8;
            int so = rr * 128 + q * 16;
            int sw = so ^ ((so >> 3) & 0x70);
            cpa16(base + 32768 + sw, B + gb);
        }
    };

    load_chunk(0, 0); cp_commit();
    load_chunk(1, 1); cp_commit();

    for (int c = 0; c < NCHUNK; c++) {
        if (c + 2 < NCHUNK) cp_wait<1>(); else cp_wait<0>();
        __syncthreads();
        if (c + 2 < NCHUNK) { load_chunk(c + 2, (c + 2) % 3); cp_commit(); }

        const unsigned sbuf = sb + (unsigned)(c % 3) * GSTG;
        const unsigned sA = sbuf, sB = sbuf + 32768;

        #pragma unroll
        for (int ks = 0; ks < 4; ks++) {
            unsigned Bf[8][2];
            #pragma unroll
            for (int jj = 0; jj < 4; jj++) {
                int off = (brow4 + jj * 16) * 128 + ks * 32 + bcol8;
                off ^= (off >> 3) & 0x70;
                unsigned tb[4];
                ldmx4(tb, sB + off);
                Bf[2*jj][0] = tb[0]; Bf[2*jj][1] = tb[1];
                Bf[2*jj+1][0] = tb[2]; Bf[2*jj+1][1] = tb[3];
            }
            #pragma unroll
            for (int mt = 0; mt < 4; mt++) {
                unsigned Af[4];
                int off = arow[mt] * 128 + ks * 32 + acolh;
                off ^= (off >> 3) & 0x70;
                ldmx4(Af, sA + off);
                #pragma unroll
                for (int j = 0; j < 8; j++)
                    mma_f16(acc[mt][j], Af, Bf[j]);
            }
        }
    }
}

// ---------------------------------------------------------------------------
// Q-projection GEMM: bias + RoPE + QSCALE + single-fp16 store
// ---------------------------------------------------------------------------
__global__ void __launch_bounds__(256) gemm_q(
    const __half* __restrict__ A, const __half* __restrict__ B,
    const float* __restrict__ bias, __half* __restrict__ qh)
{
    extern __shared__ __align__(128) char smem[];
    const int m0 = blockIdx.y * 256, n0 = blockIdx.x * 128;
    float acc[4][8][4];
    gemm_mainloop(A, B, m0, n0, smem, acc);

    const int lane = threadIdx.x & 31, w = threadIdx.x >> 5;
    const int wm = w & 3, wn = w >> 2;
    #pragma unroll
    for (int j = 0; j < 8; j++) {
        int col = n0 + wn*64 + j*8 + (lane & 3) * 2;    // even
        float bx = bias[col], by = bias[col + 1];
        float inv = exp2f((float)(col & 127) * NEG_L2_ROPE);
        #pragma unroll
        for (int mt = 0; mt < 4; mt++) {
            int r0 = m0 + wm*64 + mt*16 + (lane >> 2);
            #pragma unroll
            for (int half = 0; half < 2; half++) {
                int r = r0 + half * 8;
                float x1 = acc[mt][j][2*half + 0] + bx;
                float x2 = acc[mt][j][2*half + 1] + by;
                float sn, cs;
                sincosf((float)(r & (SEQ-1)) * inv, &sn, &cs);
                float o1 = (x1*cs - x2*sn) * QSCALE;
                float o2 = (x1*sn + x2*cs) * QSCALE;
                *(__half2*)(qh + (size_t)r * DM + col) = __floats2half2_rn(o1, o2);
            }
        }
    }
}

// ---------------------------------------------------------------------------
// K+V projection: grid (2, 32); x==0 -> K (rope + kh fp32 + single fp16),
// x==1 -> V (vh fp32 + transposed single fp16). 256x128 tiles.
// ---------------------------------------------------------------------------
__global__ void __launch_bounds__(256) gemm_kv(
    const __half* __restrict__ A,
    const __half* __restrict__ wkT, const __half* __restrict__ wvT,
    const float* __restrict__ bk, const float* __restrict__ bv,
    float* __restrict__ khout, __half* __restrict__ kh16,
    float* __restrict__ vhout, __half* __restrict__ vt16)
{
    extern __shared__ __align__(128) char smem[];
    const int m0 = blockIdx.y * 256;
    const bool isK = (blockIdx.x == 0);
    const __half* B = isK ? wkT : wvT;
    const float* bias = isK ? bk : bv;

    float acc[4][8][4];
    gemm_mainloop(A, B, m0, 0, smem, acc);

    const int lane = threadIdx.x & 31, w = threadIdx.x >> 5;
    const int wm = w & 3, wn = w >> 2;
    #pragma unroll
    for (int j = 0; j < 8; j++) {
        int col = wn*64 + j*8 + (lane & 3) * 2;    // 0..126 even
        float bx = bias[col], by = bias[col + 1];
        float inv = exp2f((float)col * NEG_L2_ROPE);
        #pragma unroll
        for (int mt = 0; mt < 4; mt++) {
            int r0 = m0 + wm*64 + mt*16 + (lane >> 2);
            #pragma unroll
            for (int half = 0; half < 2; half++) {
                int r = r0 + half * 8;
                float x1 = acc[mt][j][2*half + 0] + bx;
                float x2 = acc[mt][j][2*half + 1] + by;
                if (isK) {
                    float sn, cs;
                    sincosf((float)(r & (SEQ-1)) * inv, &sn, &cs);
                    float o1 = x1*cs - x2*sn;
                    float o2 = x1*sn + x2*cs;
                    float2 of; of.x = o1; of.y = o2;
                    *(float2*)(khout + (size_t)r * HD + col) = of;
                    *(__half2*)(kh16 + (size_t)r * HD + col) =
                        __floats2half2_rn(o1, o2);
                } else {
                    float2 of; of.x = x1; of.y = x2;
                    *(float2*)(vhout + (size_t)r * HD + col) = of;
                    int b = r >> 11, s = r & (SEQ-1);
                    vt16[((size_t)b*HD + col    ) * SEQ + s] = __float2half_rn(x1);
                    vt16[((size_t)b*HD + col + 1) * SEQ + s] = __float2half_rn(x2);
                }
            }
        }
    }
}

// ---------------------------------------------------------------------------
// O-projection GEMM: plain bias + fp32 store. 256x128 tiles.
// ---------------------------------------------------------------------------
__global__ void __launch_bounds__(256) gemm_out(
    const __half* __restrict__ A, const __half* __restrict__ B,
    const float* __restrict__ bias, float* __restrict__ C)
{
    extern __shared__ __align__(128) char smem[];
    const int m0 = blockIdx.y * 256, n0 = blockIdx.x * 128;
    float acc[4][8][4];
    gemm_mainloop(A, B, m0, n0, smem, acc);

    const int lane = threadIdx.x & 31, w = threadIdx.x >> 5;
    const int wm = w & 3, wn = w >> 2;
    #pragma unroll
    for (int mt = 0; mt < 4; mt++) {
        int r0 = m0 + wm*64 + mt*16 + (lane >> 2);
        #pragma unroll
        for (int j = 0; j < 8; j++) {
            int col = n0 + wn*64 + j*8 + (lane & 3) * 2;
            float2 o0, o1;
            o0.x = acc[mt][j][0] + bias[col];
            o0.y = acc[mt][j][1] + bias[col + 1];
            o1.x = acc[mt][j][2] + bias[col];
            o1.y = acc[mt][j][3] + bias[col + 1];
            *(float2*)(C + (size_t)r0 * DM + col)       = o0;
            *(float2*)(C + (size_t)(r0 + 8) * DM + col) = o1;
        }
    }
}

// ---------------------------------------------------------------------------
// fp32 -> single fp16 cast (elementwise) — for input x
// ---------------------------------------------------------------------------
__global__ void convert16(const float* __restrict__ a, __half* __restrict__ o)
{
    size_t i = ((size_t)blockIdx.x * blockDim.x + threadIdx.x) * 4;
    float4 v = *(const float4*)(a + i);
    *(__half2*)(o + i)     = __floats2half2_rn(v.x, v.y);
    *(__half2*)(o + i + 2) = __floats2half2_rn(v.z, v.w);
}

// ---------------------------------------------------------------------------
// weight transpose:  w[K,N] fp32  ->  single fp16 [N,K]
// ---------------------------------------------------------------------------
__global__ void transpose_w(const float* __restrict__ w,
                            __half* __restrict__ o16,
                            int K, int N)
{
    __shared__ float tile[32][33];
    const int k0 = blockIdx.x * 32, n0 = blockIdx.y * 32;
    const int tx = threadIdx.x, ty = threadIdx.y;   // 32 x 8
    #pragma unroll
    for (int i = 0; i < 32; i += 8)
        tile[ty + i][tx] = w[(size_t)(k0 + ty + i) * N + n0 + tx];
    __syncthreads();
    #pragma unroll
    for (int i = 0; i < 32; i += 8)
        o16[(size_t)(n0 + ty + i) * K + k0 + tx] =
            __float2half_rn(tile[tx][ty + i]);
}

// ---------------------------------------------------------------------------
// Tensor-core causal MQA flash attention — fully single fp16, fp32 softmax
// (m == 0, ex2 with log2e pre-folded into Q). 3-stage KV ring, one sync/tile.
// Interior tiles (kb+64 <= row0) take an unmasked fast path.
// ---------------------------------------------------------------------------
#define PQ  136                      // Q/K smem pitch (fp16 elems)
#define QELEMS (128*PQ)              // 17408 halfs (Q single)
#define KVELEMS (64*PQ + 128*64)     // K single padded + V single SW128: 16896

__global__ void __launch_bounds__(256) flash_tc(
    const __half* __restrict__ Qh, const __half* __restrict__ Kh,
    const __half* __restrict__ Vt, __half* __restrict__ O)
{
    extern __shared__ __align__(128) __half sm[];
    __half* QH = sm;                    // 128 x PQ

    const int tid = threadIdx.x;
    const int lane = tid & 31, w = tid >> 5;
    const int b = blockIdx.z, h = blockIdx.y;
    const int qb = (int)gridDim.x - 1 - (int)blockIdx.x;   // heavy CTAs first
    const int row0 = qb * 128;
    const int n_tiles = 2*qb + 2;

    auto load_kv = [&](int t, int st) {
        __half* base = sm + QELEMS + st * KVELEMS;
        const unsigned vb = s2u(base + 64*PQ);
        const int kb = t * 64;
        #pragma unroll
        for (int tt = 0; tt < 4; tt++) {
            int u = tid + tt*256;
            {   // K: 64 rows x 128 cols fp16, padded pitch
                int r = u >> 4, c = (u & 15) * 8;
                cpa16(s2u(base + r*PQ + c), Kh + ((size_t)b*SEQ + kb + r)*HD + c);
            }
            {   // V: 128 rows (hd) x 64 cols (kv) fp16, SW128 swizzle
                int r = u >> 3, c8 = u & 7;
                size_t g = ((size_t)b*HD + r)*SEQ + kb + c8*8;
                int so = r*128 + c8*16;
                int sw = so ^ ((so >> 3) & 0x70);
                cpa16(vb + sw, Vt + g);
            }
        }
    };

    load_kv(0, 0); cp_commit();
    load_kv(1, 1); cp_commit();

    // stage Q (single fp16)
    #pragma unroll
    for (int t = 0; t < 8; t++) {
        int u = tid + t*256;
        int r = u >> 4, c = (u & 15) * 8;
        size_t g = (((size_t)b*SEQ + row0 + r)*NH + h)*HD + c;
        *(uint4*)&QH[r*PQ + c] = *(const uint4*)&Qh[g];
    }
    __syncthreads();

    // Q fragments in registers (warp rows [w*16, w*16+16))
    unsigned qf[8][4];
    {
        const int ar = w*16 + (lane & 7) + ((lane >> 3) & 1) * 8;
        const int ac = (lane >> 4) * 8;
        #pragma unroll
        for (int kt = 0; kt < 8; kt++)
            ldmx4(qf[kt], s2u(&QH[ar*PQ + kt*16 + ac]));
    }

    float l0 = 0.f, l1 = 0.f;
    float o[16][4];
    #pragma unroll
    for (int n = 0; n < 16; n++)
        #pragma unroll
        for (int e = 0; e < 4; e++) o[n][e] = 0.f;

    const int qr0 = row0 + w*16 + (lane >> 2);
    const int qr1 = qr0 + 8;
    const int kcol = 2*(lane & 3);
    const int krow4 = (lane & 7) + ((lane >> 4) & 1) * 8;
    const int kchalf = ((lane >> 3) & 1) * 8;

    for (int t = 0; t < n_tiles; t++) {
        const int kb = t*64;
        if (t + 2 < n_tiles) cp_wait<1>(); else cp_wait<0>();
        __syncthreads();
        if (t + 2 < n_tiles) { load_kv(t + 2, (t + 2) % 3); cp_commit(); }

        __half* base = sm + QELEMS + (t % 3) * KVELEMS;
        __half* KH = base;
        const unsigned vb = s2u(base + 64*PQ);

        // S = Q K^T  (single fp16)
        float s[8][4];
        #pragma unroll
        for (int j = 0; j < 8; j++)
            #pragma unroll
            for (int e = 0; e < 4; e++) s[j][e] = 0.f;

        #pragma unroll
        for (int kt = 0; kt < 8; kt++) {
            #pragma unroll
            for (int jj = 0; jj < 4; jj++) {
                unsigned th[4];
                int off = (jj*16 + krow4)*PQ + kt*16 + kchalf;
                ldmx4(th, s2u(&KH[off]));
                mma_f16(s[2*jj],   qf[kt], &th[0]);
                mma_f16(s[2*jj+1], qf[kt], &th[2]);
            }
        }

        // PV helper (shared by both softmax paths)
        auto pv = [&](int ks, const unsigned aH[4]) {
            #pragma unroll
            for (int nn = 0; nn < 8; nn++) {
                unsigned vh4[4];
                int so = (nn*16 + krow4)*128 + ks*32 + kchalf*2;
                int sw = so ^ ((so >> 3) & 0x70);
                ldmx4(vh4, vb + sw);
                mma_f16(o[2*nn],   aH, &vh4[0]);
                mma_f16(o[2*nn+1], aH, &vh4[2]);
            }
        };

        if (kb + 64 <= row0) {
            // interior tile: no causal mask
            #pragma unroll
            for (int ks = 0; ks < 4; ks++) {
                unsigned aH[4];
                #pragma unroll
                for (int jj = 0; jj < 2; jj++) {
                    int j = 2*ks + jj;
                    float p0 = ex2f(s[j][0]);
                    float p1 = ex2f(s[j][1]);
                    float p2 = ex2f(s[j][2]);
                    float p3 = ex2f(s[j][3]);
                    l0 += p0 + p1; l1 += p2 + p3;
                    aH[2*jj]   = pack_h2(p0, p1);
                    aH[2*jj+1] = pack_h2(p2, p3);
                }
                pv(ks, aH);
            }
        } else {
            // boundary tile: causal mask
            #pragma unroll
            for (int ks = 0; ks < 4; ks++) {
                unsigned aH[4];
                #pragma unroll
                for (int jj = 0; jj < 2; jj++) {
                    int j = 2*ks + jj;
                    int c0 = kb + j*8 + kcol;
                    float p0 = (c0     <= qr0) ? ex2f(s[j][0]) : 0.f;
                    float p1 = (c0 + 1 <= qr0) ? ex2f(s[j][1]) : 0.f;
                    float p2 = (c0     <= qr1) ? ex2f(s[j][2]) : 0.f;
                    float p3 = (c0 + 1 <= qr1) ? ex2f(s[j][3]) : 0.f;
                    l0 += p0 + p1; l1 += p2 + p3;
                    aH[2*jj]   = pack_h2(p0, p1);
                    aH[2*jj+1] = pack_h2(p2, p3);
                }
                pv(ks, aH);
            }
        }
    }

    // reduce l across the quad once, then write single fp16 output
    l0 += __shfl_xor_sync(0xffffffffu, l0, 1);
    l0 += __shfl_xor_sync(0xffffffffu, l0, 2);
    l1 += __shfl_xor_sync(0xffffffffu, l1, 1);
    l1 += __shfl_xor_sync(0xffffffffu, l1, 2);
    const float i0 = 1.f / l0, i1 = 1.f / l1;
    #pragma unroll
    for (int n = 0; n < 16; n++) {
        int col = n*8 + kcol;
        size_t g0 = (((size_t)b*SEQ + qr0)*NH + h)*HD + col;
        size_t g1 = (((size_t)b*SEQ + qr1)*NH + h)*HD + col;
        *(__half2*)(O + g0) = __floats2half2_rn(o[n][0]*i0, o[n][1]*i0);
        *(__half2*)(O + g1) = __floats2half2_rn(o[n][2]*i1, o[n][3]*i1);
    }
}

// ---------------------------------------------------------------------------
extern "C" void kernel_launch(void* const* d_in, const int* in_sizes, int n_in,
                              void* d_out, int out_size)
{
    const float* x  = (const float*)d_in[0];
    const float* wq = (const float*)d_in[1];
    const float* bq = (const float*)d_in[2];
    const float* wk = (const float*)d_in[3];
    const float* bk = (const float*)d_in[4];
    const float* wv = (const float*)d_in[5];
    const float* bv = (const float*)d_in[6];
    const float* wo = (const float*)d_in[7];
    const float* bo = (const float*)d_in[8];

    float* out = (float*)d_out;                      // (B,S,D)
    float* kh  = out + (size_t)MROWS*DM;             // (B,1,S,HD)
    float* vh  = kh  + (size_t)MROWS*HD;             // (B,1,S,HD)

    __half *a16, *wqT, *wkT, *wvT, *woT, *qh, *kh16, *vt16;
    cudaGetSymbolAddress((void**)&a16, g_a16);
    cudaGetSymbolAddress((void**)&wqT, g_wqT);
    cudaGetSymbolAddress((void**)&wkT, g_wkT);
    cudaGetSymbolAddress((void**)&wvT, g_wvT);
    cudaGetSymbolAddress((void**)&woT, g_woT);
    cudaGetSymbolAddress((void**)&qh, g_qh);
    cudaGetSymbolAddress((void**)&kh16, g_kh16);
    cudaGetSymbolAddress((void**)&vt16, g_vt16);

    const int GEMM_SMEM  = 3 * (int)GSTG;                // 147,456 B
    const int FLASH_SMEM = (QELEMS + 3*KVELEMS) * 2;     // 136,192 B
    cudaFuncSetAttribute(gemm_q,   cudaFuncAttributeMaxDynamicSharedMemorySize, GEMM_SMEM);
    cudaFuncSetAttribute(gemm_kv,  cudaFuncAttributeMaxDynamicSharedMemorySize, GEMM_SMEM);
    cudaFuncSetAttribute(gemm_out, cudaFuncAttributeMaxDynamicSharedMemorySize, GEMM_SMEM);
    cudaFuncSetAttribute(flash_tc, cudaFuncAttributeMaxDynamicSharedMemorySize, FLASH_SMEM);

    // cast input to fp16; transpose+round weights to single fp16
    convert16<<<(size_t)MROWS*DM/1024, 256>>>(x, a16);
    transpose_w<<<dim3(DM/32, DM/32), dim3(32,8)>>>(wq, wqT, DM, DM);
    transpose_w<<<dim3(DM/32, HD/32), dim3(32,8)>>>(wk, wkT, DM, HD);
    transpose_w<<<dim3(DM/32, HD/32), dim3(32,8)>>>(wv, wvT, DM, HD);
    transpose_w<<<dim3(DM/32, DM/32), dim3(32,8)>>>(wo, woT, DM, DM);

    // projections (pure fp16, 256x128 tiles; rope/scale fused in epilogues)
    gemm_q <<<dim3(16, MROWS/256), 256, GEMM_SMEM>>>(a16, wqT, bq, qh);
    gemm_kv<<<dim3(2,  MROWS/256), 256, GEMM_SMEM>>>(a16, wkT, wvT,
                                                     bk, bv, kh, kh16, vh, vt16);

    // attention (single fp16; writes single fp16)
    flash_tc<<<dim3(16, 16, 4), 256, FLASH_SMEM>>>(qh, kh16, vt16, a16);

    // output projection
    gemm_out<<<dim3(16, MROWS/256), 256, GEMM_SMEM>>>(a16, woT, bo, out);
}

// round 16
// speedup vs baseline: 1.2080x; 1.2080x over previous
#include <cuda_runtime.h>
#include <cuda_fp16.h>
#include <math.h>

#define BATCH 4
#define SEQ   2048
#define NH    16
#define HD    128
#define DM    2048
#define MROWS (BATCH*SEQ)
#define KDIM  2048
#define NCHUNK (KDIM/64)
#define ATT_SCALE 0.08838834764831845f
#define QSCALE (ATT_SCALE * 1.4426950408889634f)   // fold log2(e) for ex2 softmax
#define NEG_L2_ROPE (-0.103810253123f)   // -log2(10000)/128

// ---------------------------------------------------------------------------
// scratch (device globals; no cudaMalloc anywhere)
// ---------------------------------------------------------------------------
__device__ __half g_a16[(size_t)MROWS*DM];   // activations fp16 (x, then attn out)
__device__ __half g_wqT[(size_t)DM*DM];      // weights, transposed, single fp16
__device__ __half g_woT[(size_t)DM*DM];
__device__ __half g_wkT[(size_t)HD*DM];
__device__ __half g_wvT[(size_t)HD*DM];
// attention operands (single fp16); q pre-scaled by QSCALE
__device__ __half g_qh[(size_t)MROWS*DM];    // [B,S,NH,HD]
__device__ __half g_kh16[(size_t)MROWS*HD];  // [B,S,HD]
__device__ __half g_vt16[(size_t)MROWS*HD];  // [B,HD,S]

// ---------------------------------------------------------------------------
// helpers
// ---------------------------------------------------------------------------
__device__ __forceinline__ unsigned s2u(const void* p) {
    unsigned a;
    asm("{ .reg .u64 t; cvta.to.shared.u64 t, %1; cvt.u32.u64 %0, t; }"
        : "=r"(a) : "l"(p));
    return a;
}
__device__ __forceinline__ void ldmx4(unsigned r[4], unsigned addr) {
    asm volatile("ldmatrix.sync.aligned.m8n8.x4.shared.b16 {%0,%1,%2,%3}, [%4];"
                 : "=r"(r[0]), "=r"(r[1]), "=r"(r[2]), "=r"(r[3]) : "r"(addr));
}
__device__ __forceinline__ void mma_f16(float c[4], const unsigned a[4],
                                        const unsigned b[2]) {
    asm volatile(
        "mma.sync.aligned.m16n8k16.row.col.f32.f16.f16.f32 "
        "{%0,%1,%2,%3}, {%4,%5,%6,%7}, {%8,%9}, {%0,%1,%2,%3};"
        : "+f"(c[0]), "+f"(c[1]), "+f"(c[2]), "+f"(c[3])
        : "r"(a[0]), "r"(a[1]), "r"(a[2]), "r"(a[3]), "r"(b[0]), "r"(b[1]));
}
__device__ __forceinline__ unsigned pack_h2(float a, float b) {
    __half2 t = __floats2half2_rn(a, b);
    return *(unsigned*)&t;
}
__device__ __forceinline__ float ex2f(float x) {
    float r;
    asm("ex2.approx.f32 %0, %1;" : "=f"(r) : "f"(x));
    return r;
}
__device__ __forceinline__ void cpa16(unsigned dst, const void* src) {
    asm volatile("cp.async.cg.shared.global [%0], [%1], 16;"
                 :: "r"(dst), "l"(src) : "memory");
}
__device__ __forceinline__ void cp_commit() {
    asm volatile("cp.async.commit_group;" ::: "memory");
}
template<int N> __device__ __forceinline__ void cp_wait() {
    asm volatile("cp.async.wait_group %0;" :: "n"(N) : "memory");
}

// ---------------------------------------------------------------------------
// pure fp16 GEMM mainloop (128x128 tile): acc = A[128,K] @ B[128,K]^T.
// 3-stage cp.async ring (32 KB/stage -> 2 CTAs/SM), one sync per chunk.
// ---------------------------------------------------------------------------
#define GSTG 32768u   // stage bytes: A 16K | B 16K

__device__ __forceinline__ void gemm_mainloop(
    const __half* __restrict__ A, const __half* __restrict__ B,
    int m0, int n0, char* smem, float acc[2][8][4])
{
    const unsigned sb = s2u(smem);
    const int tid = threadIdx.x;
    const int lane = tid & 31, w = tid >> 5;
    const int wm = w & 3, wn = w >> 2;

    #pragma unroll
    for (int mt = 0; mt < 2; mt++)
        #pragma unroll
        for (int j = 0; j < 8; j++)
            #pragma unroll
            for (int e = 0; e < 4; e++) acc[mt][j][e] = 0.f;

    int arow[2];
    #pragma unroll
    for (int mt = 0; mt < 2; mt++)
        arow[mt] = wm*32 + mt*16 + (lane & 7) + ((lane >> 3) & 1) * 8;
    const int acolh = (lane >> 4) * 16;
    const int brow4 = wn*64 + (lane & 7) + ((lane >> 4) & 1) * 8;
    const int bcol8 = ((lane >> 3) & 1) * 16;

    auto load_chunk = [&](int c, int st) {
        const int k0 = c * 64;
        const unsigned base = sb + (unsigned)st * GSTG;
        #pragma unroll
        for (int t = 0; t < 4; t++) {
            int i = tid + t * 256;
            int rr = i >> 3, q = i & 7;
            size_t ga = (size_t)(m0 + rr) * KDIM + k0 + q * 8;
            size_t gb = (size_t)(n0 + rr) * KDIM + k0 + q * 8;
            int so = rr * 128 + q * 16;
            int sw = so ^ ((so >> 3) & 0x70);
            cpa16(base + sw,          A + ga);
            cpa16(base + 16384 + sw,  B + gb);
        }
    };

    load_chunk(0, 0); cp_commit();
    load_chunk(1, 1); cp_commit();

    for (int c = 0; c < NCHUNK; c++) {
        if (c + 2 < NCHUNK) cp_wait<1>(); else cp_wait<0>();
        __syncthreads();
        if (c + 2 < NCHUNK) { load_chunk(c + 2, (c + 2) % 3); cp_commit(); }

        const unsigned sbuf = sb + (unsigned)(c % 3) * GSTG;
        const unsigned sA = sbuf, sB = sbuf + 16384;

        #pragma unroll
        for (int ks = 0; ks < 4; ks++) {
            unsigned Af[2][4], Bf[8][2];
            #pragma unroll
            for (int mt = 0; mt < 2; mt++) {
                int off = arow[mt] * 128 + ks * 32 + acolh;
                off ^= (off >> 3) & 0x70;
                ldmx4(Af[mt], sA + off);
            }
            #pragma unroll
            for (int jj = 0; jj < 4; jj++) {
                int off = (brow4 + jj * 16) * 128 + ks * 32 + bcol8;
                off ^= (off >> 3) & 0x70;
                unsigned tb[4];
                ldmx4(tb, sB + off);
                Bf[2*jj][0] = tb[0]; Bf[2*jj][1] = tb[1];
                Bf[2*jj+1][0] = tb[2]; Bf[2*jj+1][1] = tb[3];
            }
            #pragma unroll
            for (int mt = 0; mt < 2; mt++)
                #pragma unroll
                for (int j = 0; j < 8; j++)
                    mma_f16(acc[mt][j], Af[mt], Bf[j]);
        }
    }
}

// ---------------------------------------------------------------------------
// Q-projection GEMM: bias + RoPE + QSCALE + single-fp16 store
// ---------------------------------------------------------------------------
__global__ void __launch_bounds__(256) gemm_q(
    const __half* __restrict__ A, const __half* __restrict__ B,
    const float* __restrict__ bias, __half* __restrict__ qh)
{
    extern __shared__ __align__(128) char smem[];
    const int m0 = blockIdx.y * 128, n0 = blockIdx.x * 128;
    float acc[2][8][4];
    gemm_mainloop(A, B, m0, n0, smem, acc);

    const int lane = threadIdx.x & 31, w = threadIdx.x >> 5;
    const int wm = w & 3, wn = w >> 2;
    #pragma unroll
    for (int j = 0; j < 8; j++) {
        int col = n0 + wn*64 + j*8 + (lane & 3) * 2;    // even
        float bx = bias[col], by = bias[col + 1];
        float inv = exp2f((float)(col & 127) * NEG_L2_ROPE);
        #pragma unroll
        for (int mt = 0; mt < 2; mt++) {
            int r0 = m0 + wm*32 + mt*16 + (lane >> 2);
            #pragma unroll
            for (int half = 0; half < 2; half++) {
                int r = r0 + half * 8;
                float x1 = acc[mt][j][2*half + 0] + bx;
                float x2 = acc[mt][j][2*half + 1] + by;
                float sn, cs;
                sincosf((float)(r & (SEQ-1)) * inv, &sn, &cs);
                float o1 = (x1*cs - x2*sn) * QSCALE;
                float o2 = (x1*sn + x2*cs) * QSCALE;
                *(__half2*)(qh + (size_t)r * DM + col) = __floats2half2_rn(o1, o2);
            }
        }
    }
}

// ---------------------------------------------------------------------------
// K+V projection: grid (2, 64); x==0 -> K (rope + kh fp32 + single fp16),
// x==1 -> V (vh fp32 + transposed single fp16).
// ---------------------------------------------------------------------------
__global__ void __launch_bounds__(256) gemm_kv(
    const __half* __restrict__ A,
    const __half* __restrict__ wkT, const __half* __restrict__ wvT,
    const float* __restrict__ bk, const float* __restrict__ bv,
    float* __restrict__ khout, __half* __restrict__ kh16,
    float* __restrict__ vhout, __half* __restrict__ vt16)
{
    extern __shared__ __align__(128) char smem[];
    const int m0 = blockIdx.y * 128;
    const bool isK = (blockIdx.x == 0);
    const __half* B = isK ? wkT : wvT;
    const float* bias = isK ? bk : bv;

    float acc[2][8][4];
    gemm_mainloop(A, B, m0, 0, smem, acc);

    const int lane = threadIdx.x & 31, w = threadIdx.x >> 5;
    const int wm = w & 3, wn = w >> 2;
    #pragma unroll
    for (int j = 0; j < 8; j++) {
        int col = wn*64 + j*8 + (lane & 3) * 2;    // 0..126 even
        float bx = bias[col], by = bias[col + 1];
        float inv = exp2f((float)col * NEG_L2_ROPE);
        #pragma unroll
        for (int mt = 0; mt < 2; mt++) {
            int r0 = m0 + wm*32 + mt*16 + (lane >> 2);
            #pragma unroll
            for (int half = 0; half < 2; half++) {
                int r = r0 + half * 8;
                float x1 = acc[mt][j][2*half + 0] + bx;
                float x2 = acc[mt][j][2*half + 1] + by;
                if (isK) {
                    float sn, cs;
                    sincosf((float)(r & (SEQ-1)) * inv, &sn, &cs);
                    float o1 = x1*cs - x2*sn;
                    float o2 = x1*sn + x2*cs;
                    float2 of; of.x = o1; of.y = o2;
                    *(float2*)(khout + (size_t)r * HD + col) = of;
                    *(__half2*)(kh16 + (size_t)r * HD + col) =
                        __floats2half2_rn(o1, o2);
                } else {
                    float2 of; of.x = x1; of.y = x2;
                    *(float2*)(vhout + (size_t)r * HD + col) = of;
                    int b = r >> 11, s = r & (SEQ-1);
                    vt16[((size_t)b*HD + col    ) * SEQ + s] = __float2half_rn(x1);
                    vt16[((size_t)b*HD + col + 1) * SEQ + s] = __float2half_rn(x2);
                }
            }
        }
    }
}

// ---------------------------------------------------------------------------
// O-projection GEMM: plain bias + fp32 store
// ---------------------------------------------------------------------------
__global__ void __launch_bounds__(256) gemm_out(
    const __half* __restrict__ A, const __half* __restrict__ B,
    const float* __restrict__ bias, float* __restrict__ C)
{
    extern __shared__ __align__(128) char smem[];
    const int m0 = blockIdx.y * 128, n0 = blockIdx.x * 128;
    float acc[2][8][4];
    gemm_mainloop(A, B, m0, n0, smem, acc);

    const int lane = threadIdx.x & 31, w = threadIdx.x >> 5;
    const int wm = w & 3, wn = w >> 2;
    #pragma unroll
    for (int mt = 0; mt < 2; mt++) {
        int r0 = m0 + wm*32 + mt*16 + (lane >> 2);
        #pragma unroll
        for (int j = 0; j < 8; j++) {
            int col = n0 + wn*64 + j*8 + (lane & 3) * 2;
            float2 o0, o1;
            o0.x = acc[mt][j][0] + bias[col];
            o0.y = acc[mt][j][1] + bias[col + 1];
            o1.x = acc[mt][j][2] + bias[col];
            o1.y = acc[mt][j][3] + bias[col + 1];
            *(float2*)(C + (size_t)r0 * DM + col)       = o0;
            *(float2*)(C + (size_t)(r0 + 8) * DM + col) = o1;
        }
    }
}

// ---------------------------------------------------------------------------
// fp32 -> single fp16 cast (elementwise) — for input x
// ---------------------------------------------------------------------------
__global__ void convert16(const float* __restrict__ a, __half* __restrict__ o)
{
    size_t i = ((size_t)blockIdx.x * blockDim.x + threadIdx.x) * 4;
    float4 v = *(const float4*)(a + i);
    *(__half2*)(o + i)     = __floats2half2_rn(v.x, v.y);
    *(__half2*)(o + i + 2) = __floats2half2_rn(v.z, v.w);
}

// ---------------------------------------------------------------------------
// weight transpose:  w[K,N] fp32  ->  single fp16 [N,K]
// ---------------------------------------------------------------------------
__global__ void transpose_w(const float* __restrict__ w,
                            __half* __restrict__ o16,
                            int K, int N)
{
    __shared__ float tile[32][33];
    const int k0 = blockIdx.x * 32, n0 = blockIdx.y * 32;
    const int tx = threadIdx.x, ty = threadIdx.y;   // 32 x 8
    #pragma unroll
    for (int i = 0; i < 32; i += 8)
        tile[ty + i][tx] = w[(size_t)(k0 + ty + i) * N + n0 + tx];
    __syncthreads();
    #pragma unroll
    for (int i = 0; i < 32; i += 8)
        o16[(size_t)(n0 + ty + i) * K + k0 + tx] =
            __float2half_rn(tile[tx][ty + i]);
}

// ---------------------------------------------------------------------------
// Tensor-core causal MQA flash attention — fully single fp16, fp32 softmax
// (m == 0, ex2 with log2e pre-folded into Q). 3-stage KV ring, one sync/tile.
// Interior tiles (kb+64 <= row0) take an unmasked fast path.
// ---------------------------------------------------------------------------
#define PQ  136                      // Q/K smem pitch (fp16 elems)
#define QELEMS (128*PQ)              // 17408 halfs (Q single)
#define KVELEMS (64*PQ + 128*64)     // K single padded + V single SW128: 16896

__global__ void __launch_bounds__(256) flash_tc(
    const __half* __restrict__ Qh, const __half* __restrict__ Kh,
    const __half* __restrict__ Vt, __half* __restrict__ O)
{
    extern __shared__ __align__(128) __half sm[];
    __half* QH = sm;                    // 128 x PQ

    const int tid = threadIdx.x;
    const int lane = tid & 31, w = tid >> 5;
    const int b = blockIdx.z, h = blockIdx.y;
    const int qb = (int)gridDim.x - 1 - (int)blockIdx.x;   // heavy CTAs first
    const int row0 = qb * 128;
    const int n_tiles = 2*qb + 2;

    auto load_kv = [&](int t, int st) {
        __half* base = sm + QELEMS + st * KVELEMS;
        const unsigned vb = s2u(base + 64*PQ);
        const int kb = t * 64;
        #pragma unroll
        for (int tt = 0; tt < 4; tt++) {
            int u = tid + tt*256;
            {   // K: 64 rows x 128 cols fp16, padded pitch
                int r = u >> 4, c = (u & 15) * 8;
                cpa16(s2u(base + r*PQ + c), Kh + ((size_t)b*SEQ + kb + r)*HD + c);
            }
            {   // V: 128 rows (hd) x 64 cols (kv) fp16, SW128 swizzle
                int r = u >> 3, c8 = u & 7;
                size_t g = ((size_t)b*HD + r)*SEQ + kb + c8*8;
                int so = r*128 + c8*16;
                int sw = so ^ ((so >> 3) & 0x70);
                cpa16(vb + sw, Vt + g);
            }
        }
    };

    load_kv(0, 0); cp_commit();
    load_kv(1, 1); cp_commit();

    // stage Q (single fp16)
    #pragma unroll
    for (int t = 0; t < 8; t++) {
        int u = tid + t*256;
        int r = u >> 4, c = (u & 15) * 8;
        size_t g = (((size_t)b*SEQ + row0 + r)*NH + h)*HD + c;
        *(uint4*)&QH[r*PQ + c] = *(const uint4*)&Qh[g];
    }
    __syncthreads();

    // Q fragments in registers (warp rows [w*16, w*16+16))
    unsigned qf[8][4];
    {
        const int ar = w*16 + (lane & 7) + ((lane >> 3) & 1) * 8;
        const int ac = (lane >> 4) * 8;
        #pragma unroll
        for (int kt = 0; kt < 8; kt++)
            ldmx4(qf[kt], s2u(&QH[ar*PQ + kt*16 + ac]));
    }

    float l0 = 0.f, l1 = 0.f;
    float o[16][4];
    #pragma unroll
    for (int n = 0; n < 16; n++)
        #pragma unroll
        for (int e = 0; e < 4; e++) o[n][e] = 0.f;

    const int qr0 = row0 + w*16 + (lane >> 2);
    const int qr1 = qr0 + 8;
    const int kcol = 2*(lane & 3);
    const int krow4 = (lane & 7) + ((lane >> 4) & 1) * 8;
    const int kchalf = ((lane >> 3) & 1) * 8;

    for (int t = 0; t < n_tiles; t++) {
        const int kb = t*64;
        if (t + 2 < n_tiles) cp_wait<1>(); else cp_wait<0>();
        __syncthreads();
        if (t + 2 < n_tiles) { load_kv(t + 2, (t + 2) % 3); cp_commit(); }

        __half* base = sm + QELEMS + (t % 3) * KVELEMS;
        __half* KH = base;
        const unsigned vb = s2u(base + 64*PQ);

        // S = Q K^T  (single fp16)
        float s[8][4];
        #pragma unroll
        for (int j = 0; j < 8; j++)
            #pragma unroll
            for (int e = 0; e < 4; e++) s[j][e] = 0.f;

        #pragma unroll
        for (int kt = 0; kt < 8; kt++) {
            #pragma unroll
            for (int jj = 0; jj < 4; jj++) {
                unsigned th[4];
                int off = (jj*16 + krow4)*PQ + kt*16 + kchalf;
                ldmx4(th, s2u(&KH[off]));
                mma_f16(s[2*jj],   qf[kt], &th[0]);
                mma_f16(s[2*jj+1], qf[kt], &th[2]);
            }
        }

        // PV helper (shared by both softmax paths)
        auto pv = [&](int ks, const unsigned aH[4]) {
            #pragma unroll
            for (int nn = 0; nn < 8; nn++) {
                unsigned vh4[4];
                int so = (nn*16 + krow4)*128 + ks*32 + kchalf*2;
                int sw = so ^ ((so >> 3) & 0x70);
                ldmx4(vh4, vb + sw);
                mma_f16(o[2*nn],   aH, &vh4[0]);
                mma_f16(o[2*nn+1], aH, &vh4[2]);
            }
        };

        if (kb + 64 <= row0) {
            // interior tile: no causal mask
            #pragma unroll
            for (int ks = 0; ks < 4; ks++) {
                unsigned aH[4];
                #pragma unroll
                for (int jj = 0; jj < 2; jj++) {
                    int j = 2*ks + jj;
                    float p0 = ex2f(s[j][0]);
                    float p1 = ex2f(s[j][1]);
                    float p2 = ex2f(s[j][2]);
                    float p3 = ex2f(s[j][3]);
                    l0 += p0 + p1; l1 += p2 + p3;
                    aH[2*jj]   = pack_h2(p0, p1);
                    aH[2*jj+1] = pack_h2(p2, p3);
                }
                pv(ks, aH);
            }
        } else {
            // boundary tile: causal mask
            #pragma unroll
            for (int ks = 0; ks < 4; ks++) {
                unsigned aH[4];
                #pragma unroll
                for (int jj = 0; jj < 2; jj++) {
                    int j = 2*ks + jj;
                    int c0 = kb + j*8 + kcol;
                    float p0 = (c0     <= qr0) ? ex2f(s[j][0]) : 0.f;
                    float p1 = (c0 + 1 <= qr0) ? ex2f(s[j][1]) : 0.f;
                    float p2 = (c0     <= qr1) ? ex2f(s[j][2]) : 0.f;
                    float p3 = (c0 + 1 <= qr1) ? ex2f(s[j][3]) : 0.f;
                    l0 += p0 + p1; l1 += p2 + p3;
                    aH[2*jj]   = pack_h2(p0, p1);
                    aH[2*jj+1] = pack_h2(p2, p3);
                }
                pv(ks, aH);
            }
        }
    }

    // reduce l across the quad once, then write single fp16 output
    l0 += __shfl_xor_sync(0xffffffffu, l0, 1);
    l0 += __shfl_xor_sync(0xffffffffu, l0, 2);
    l1 += __shfl_xor_sync(0xffffffffu, l1, 1);
    l1 += __shfl_xor_sync(0xffffffffu, l1, 2);
    const float i0 = 1.f / l0, i1 = 1.f / l1;
    #pragma unroll
    for (int n = 0; n < 16; n++) {
        int col = n*8 + kcol;
        size_t g0 = (((size_t)b*SEQ + qr0)*NH + h)*HD + col;
        size_t g1 = (((size_t)b*SEQ + qr1)*NH + h)*HD + col;
        *(__half2*)(O + g0) = __floats2half2_rn(o[n][0]*i0, o[n][1]*i0);
        *(__half2*)(O + g1) = __floats2half2_rn(o[n][2]*i1, o[n][3]*i1);
    }
}

// ---------------------------------------------------------------------------
extern "C" void kernel_launch(void* const* d_in, const int* in_sizes, int n_in,
                              void* d_out, int out_size)
{
    const float* x  = (const float*)d_in[0];
    const float* wq = (const float*)d_in[1];
    const float* bq = (const float*)d_in[2];
    const float* wk = (const float*)d_in[3];
    const float* bk = (const float*)d_in[4];
    const float* wv = (const float*)d_in[5];
    const float* bv = (const float*)d_in[6];
    const float* wo = (const float*)d_in[7];
    const float* bo = (const float*)d_in[8];

    float* out = (float*)d_out;                      // (B,S,D)
    float* kh  = out + (size_t)MROWS*DM;             // (B,1,S,HD)
    float* vh  = kh  + (size_t)MROWS*HD;             // (B,1,S,HD)

    __half *a16, *wqT, *wkT, *wvT, *woT, *qh, *kh16, *vt16;
    cudaGetSymbolAddress((void**)&a16, g_a16);
    cudaGetSymbolAddress((void**)&wqT, g_wqT);
    cudaGetSymbolAddress((void**)&wkT, g_wkT);
    cudaGetSymbolAddress((void**)&wvT, g_wvT);
    cudaGetSymbolAddress((void**)&woT, g_woT);
    cudaGetSymbolAddress((void**)&qh, g_qh);
    cudaGetSymbolAddress((void**)&kh16, g_kh16);
    cudaGetSymbolAddress((void**)&vt16, g_vt16);

    const int GEMM_SMEM  = 3 * (int)GSTG;                // 98,304 B (2 CTAs/SM)
    const int FLASH_SMEM = (QELEMS + 3*KVELEMS) * 2;     // 136,192 B
    cudaFuncSetAttribute(gemm_q,   cudaFuncAttributeMaxDynamicSharedMemorySize, GEMM_SMEM);
    cudaFuncSetAttribute(gemm_kv,  cudaFuncAttributeMaxDynamicSharedMemorySize, GEMM_SMEM);
    cudaFuncSetAttribute(gemm_out, cudaFuncAttributeMaxDynamicSharedMemorySize, GEMM_SMEM);
    cudaFuncSetAttribute(flash_tc, cudaFuncAttributeMaxDynamicSharedMemorySize, FLASH_SMEM);

    // cast input to fp16; transpose+round weights to single fp16
    convert16<<<(size_t)MROWS*DM/1024, 256>>>(x, a16);
    transpose_w<<<dim3(DM/32, DM/32), dim3(32,8)>>>(wq, wqT, DM, DM);
    transpose_w<<<dim3(DM/32, HD/32), dim3(32,8)>>>(wk, wkT, DM, HD);
    transpose_w<<<dim3(DM/32, HD/32), dim3(32,8)>>>(wv, wvT, DM, HD);
    transpose_w<<<dim3(DM/32, DM/32), dim3(32,8)>>>(wo, woT, DM, DM);

    // projections (pure fp16, 128x128 tiles @ 2 CTAs/SM)
    gemm_q <<<dim3(16, MROWS/128), 256, GEMM_SMEM>>>(a16, wqT, bq, qh);
    gemm_kv<<<dim3(2,  MROWS/128), 256, GEMM_SMEM>>>(a16, wkT, wvT,
                                                     bk, bv, kh, kh16, vh, vt16);

    // attention (single fp16; writes single fp16)
    flash_tc<<<dim3(16, 16, 4), 256, FLASH_SMEM>>>(qh, kh16, vt16, a16);

    // output projection
    gemm_out<<<dim3(16, MROWS/128), 256, GEMM_SMEM>>>(a16, woT, bo, out);
}